// round 15
// baseline (speedup 1.0000x reference)
#include <cuda_runtime.h>
#include <cuda_bf16.h>
#include <cuda_fp8.h>
#include <stdint.h>
#include <math.h>

#define N_NODES 50000
#define N_EDGES 800000
#define C_IN    768
#define C1      256
#define C2      128
#define C3      2

#define SCAN_T  1024
#define SCAN_CH ((N_NODES + SCAN_T - 1) / SCAN_T)   // 49

// ---------------- scratch (device globals; no allocation allowed) ----------
__device__ float g_dinv[N_NODES];
__device__ int   g_cnt[N_NODES];            // counts, then write cursor
__device__ int   g_off[N_NODES + 1];
__device__ int   g_csr[N_EDGES];            // src ids grouped by dst
__device__ __nv_fp8_storage_t g_h1[(size_t)N_NODES * C1];   // x@W1 (e4m3)
__device__ __nv_bfloat16 g_a1[(size_t)N_NODES * C1];        // relu(A h1 + b1) (bf16)
__device__ __nv_fp8_storage_t g_h2[(size_t)N_NODES * C2];   // a1@W2 (e4m3)
__device__ float g_h3[(size_t)N_NODES * C3];

// ---------------- fp8 helpers -----------------------------------------------
__device__ __forceinline__ float2 fp8x2_to_float2(unsigned short v) {
    __half2_raw hr = __nv_cvt_fp8x2_to_halfraw2((__nv_fp8x2_storage_t)v, __NV_E4M3);
    return __half22float2(*(__half2*)&hr);
}

__device__ __forceinline__ unsigned short float2_to_fp8x2(float a, float b) {
    return (unsigned short)__nv_cvt_float2_to_fp8x2(make_float2(a, b),
                                                    __NV_SATFINITE, __NV_E4M3);
}

// ---------------- CSR build -------------------------------------------------
__global__ void k_zero_cnt() {
    int i = blockIdx.x * blockDim.x + threadIdx.x;
    if (i < N_NODES) g_cnt[i] = 0;
}

__global__ void k_count(const int* __restrict__ dst) {
    int e = blockIdx.x * blockDim.x + threadIdx.x;
    if (e < N_EDGES) atomicAdd(&g_cnt[dst[e]], 1);
}

__global__ void __launch_bounds__(SCAN_T) k_scan() {
    __shared__ int s_part[SCAN_T];
    const int t = threadIdx.x;
    const int start = t * SCAN_CH;
    const int end   = min(start + SCAN_CH, N_NODES);

    int sum = 0;
    for (int i = start; i < end; i++) {
        int c = g_cnt[i];
        sum += c;
        g_dinv[i] = rsqrtf((float)(c + 1));   // +1 self loop
    }
    s_part[t] = sum;
    __syncthreads();
    for (int ofs = 1; ofs < SCAN_T; ofs <<= 1) {
        int v = 0;
        if (t >= ofs) v = s_part[t - ofs];
        __syncthreads();
        if (t >= ofs) s_part[t] += v;
        __syncthreads();
    }
    int run = (t == 0) ? 0 : s_part[t - 1];
    for (int i = start; i < end; i++) {
        int c = g_cnt[i];
        g_off[i] = run;
        g_cnt[i] = run;       // cursor for k_fill
        run += c;
    }
    if (start < N_NODES && end == N_NODES) g_off[N_NODES] = run;
}

__global__ void k_fill(const int* __restrict__ src, const int* __restrict__ dst) {
    int e = blockIdx.x * blockDim.x + threadIdx.x;
    if (e < N_EDGES) {
        int pos = atomicAdd(&g_cnt[dst[e]], 1);
        g_csr[pos] = src[e];
    }
}

// ---------------- BF16 tensor-core GEMM (k-pair packed smem), fp8 out -------
__device__ __forceinline__ unsigned pack_bf16(float lo, float hi) {
    __nv_bfloat162 v = __floats2bfloat162_rn(lo, hi);
    return *(unsigned*)&v;
}

// ===== 512-thread variant: BM=128, BN=256, fp32 A (layer 1) =================
__global__ void __launch_bounds__(512) bf16_gemm_n256(const float* __restrict__ A,
                                                      const float* __restrict__ B,
                                                      __nv_fp8_storage_t* __restrict__ Cout,
                                                      int M, int K) {
    const int N = 256;
    __shared__ unsigned As_p[2][128][12];
    __shared__ unsigned Bs_p[2][8][264];

    const int tid  = threadIdx.x;
    const int warp = tid >> 5;
    const int lane = tid & 31;
    const int gid  = lane >> 2;
    const int tig  = lane & 3;
    const int wm   = warp & 1;
    const int wn   = warp >> 1;
    const int bm   = blockIdx.y * 128;

    const int am  = tid >> 2;
    const int akq = tid & 3;
    const int bk2 = tid >> 6;
    const int bn4 = (tid & 63) * 4;

    float acc[4][4][4];
#pragma unroll
    for (int i = 0; i < 4; i++)
#pragma unroll
        for (int j = 0; j < 4; j++)
#pragma unroll
            for (int q = 0; q < 4; q++) acc[i][j][q] = 0.0f;

    const int nIter = K / 16;
    float4 la, lb0, lb1;

    auto load_regs = [&](int it) {
        int k0 = it * 16;
        if (bm + am < M)
            la = *(const float4*)(A + (size_t)(bm + am) * K + k0 + akq * 4);
        else
            la = make_float4(0.f, 0.f, 0.f, 0.f);
        const float* bp = B + (size_t)(k0 + 2 * bk2) * N + bn4;
        lb0 = *(const float4*)bp;
        lb1 = *(const float4*)(bp + N);
    };

    auto store_smem = [&](int buf) {
        unsigned ua0 = pack_bf16(la.x, la.y);
        unsigned ua1 = pack_bf16(la.z, la.w);
        *(uint2*)&As_p[buf][am][akq * 2] = make_uint2(ua0, ua1);
        unsigned ub0 = pack_bf16(lb0.x, lb1.x);
        unsigned ub1 = pack_bf16(lb0.y, lb1.y);
        unsigned ub2 = pack_bf16(lb0.z, lb1.z);
        unsigned ub3 = pack_bf16(lb0.w, lb1.w);
        *(uint4*)&Bs_p[buf][bk2][bn4] = make_uint4(ub0, ub1, ub2, ub3);
    };

    load_regs(0);
    store_smem(0);
    __syncthreads();

    for (int it = 0; it < nIter; it++) {
        int buf = it & 1;
        bool hasNext = (it + 1) < nIter;
        if (hasNext) load_regs(it + 1);

        unsigned af[4][4], bf[4][2];
#pragma unroll
        for (int im = 0; im < 4; im++) {
            int m = wm * 64 + im * 16 + gid;
            af[im][0] = As_p[buf][m][tig];
            af[im][1] = As_p[buf][m + 8][tig];
            af[im][2] = As_p[buf][m][tig + 4];
            af[im][3] = As_p[buf][m + 8][tig + 4];
        }
#pragma unroll
        for (int in_ = 0; in_ < 4; in_++) {
            int n = wn * 32 + in_ * 8 + gid;
            bf[in_][0] = Bs_p[buf][tig][n];
            bf[in_][1] = Bs_p[buf][tig + 4][n];
        }
#pragma unroll
        for (int im = 0; im < 4; im++)
#pragma unroll
            for (int in_ = 0; in_ < 4; in_++) {
                asm volatile(
                    "mma.sync.aligned.m16n8k16.row.col.f32.bf16.bf16.f32 "
                    "{%0,%1,%2,%3}, {%4,%5,%6,%7}, {%8,%9}, {%0,%1,%2,%3};"
                    : "+f"(acc[im][in_][0]), "+f"(acc[im][in_][1]),
                      "+f"(acc[im][in_][2]), "+f"(acc[im][in_][3])
                    : "r"(af[im][0]), "r"(af[im][1]),
                      "r"(af[im][2]), "r"(af[im][3]),
                      "r"(bf[in_][0]), "r"(bf[in_][1]));
            }

        if (hasNext) {
            store_smem((it + 1) & 1);
            __syncthreads();
        }
    }

#pragma unroll
    for (int im = 0; im < 4; im++) {
        int r0 = bm + wm * 64 + im * 16 + gid;
        int r1 = r0 + 8;
#pragma unroll
        for (int in_ = 0; in_ < 4; in_++) {
            int c = wn * 32 + in_ * 8 + 2 * tig;
            if (r0 < M)
                *(unsigned short*)(Cout + (size_t)r0 * N + c) =
                    float2_to_fp8x2(acc[im][in_][0], acc[im][in_][1]);
            if (r1 < M)
                *(unsigned short*)(Cout + (size_t)r1 * N + c) =
                    float2_to_fp8x2(acc[im][in_][2], acc[im][in_][3]);
        }
    }
}

// ===== 256-thread variant: BM=128, BN=128, A already bf16 k-pair packed =====
// A is [M, K] bf16 row-major: adjacent (k, k+1) bf16 = one packed uint in gmem,
// so A-staging is a direct uint4 copy (no conversion).
__global__ void __launch_bounds__(256) bf16_gemm_abf16(const __nv_bfloat16* __restrict__ A,
                                                       const float* __restrict__ B,
                                                       __nv_fp8_storage_t* __restrict__ Cout,
                                                       int M, int K, int N) {
    __shared__ unsigned As_p[2][128][12];
    __shared__ unsigned Bs_p[2][8][136];

    const int tid  = threadIdx.x;
    const int warp = tid >> 5;
    const int lane = tid & 31;
    const int gid  = lane >> 2;
    const int tig  = lane & 3;
    const int wm   = warp & 1;
    const int wn   = warp >> 1;
    const int bm   = blockIdx.y * 128;
    const int bn   = blockIdx.x * 128;

    const int am = tid >> 1;          // A row 0..127
    const int akh = tid & 1;          // which half of the 8 k-pairs
    const int bw = warp;
    const int bn4 = lane * 4;

    float acc[4][4][4];
#pragma unroll
    for (int i = 0; i < 4; i++)
#pragma unroll
        for (int j = 0; j < 4; j++)
#pragma unroll
            for (int q = 0; q < 4; q++) acc[i][j][q] = 0.0f;

    const int nIter = K / 16;
    uint4 laq;
    float4 lb0, lb1;

    auto load_regs = [&](int it) {
        if (bm + am < M)
            laq = ((const uint4*)(A + (size_t)(bm + am) * K))[it * 2 + akh];
        else
            laq = make_uint4(0u, 0u, 0u, 0u);
        int k0 = it * 16;
        const float* bp = B + (size_t)(k0 + 2 * bw) * N + bn + bn4;
        lb0 = *(const float4*)bp;
        lb1 = *(const float4*)(bp + N);
    };

    auto store_smem = [&](int buf) {
        *(uint4*)&As_p[buf][am][akh * 4] = laq;
        unsigned ub0 = pack_bf16(lb0.x, lb1.x);
        unsigned ub1 = pack_bf16(lb0.y, lb1.y);
        unsigned ub2 = pack_bf16(lb0.z, lb1.z);
        unsigned ub3 = pack_bf16(lb0.w, lb1.w);
        *(uint4*)&Bs_p[buf][bw][bn4] = make_uint4(ub0, ub1, ub2, ub3);
    };

    load_regs(0);
    store_smem(0);
    __syncthreads();

    for (int it = 0; it < nIter; it++) {
        int buf = it & 1;
        bool hasNext = (it + 1) < nIter;
        if (hasNext) load_regs(it + 1);

        unsigned af[4][4], bf[4][2];
#pragma unroll
        for (int im = 0; im < 4; im++) {
            int m = wm * 64 + im * 16 + gid;
            af[im][0] = As_p[buf][m][tig];
            af[im][1] = As_p[buf][m + 8][tig];
            af[im][2] = As_p[buf][m][tig + 4];
            af[im][3] = As_p[buf][m + 8][tig + 4];
        }
#pragma unroll
        for (int in_ = 0; in_ < 4; in_++) {
            int n = wn * 32 + in_ * 8 + gid;
            bf[in_][0] = Bs_p[buf][tig][n];
            bf[in_][1] = Bs_p[buf][tig + 4][n];
        }
#pragma unroll
        for (int im = 0; im < 4; im++)
#pragma unroll
            for (int in_ = 0; in_ < 4; in_++) {
                asm volatile(
                    "mma.sync.aligned.m16n8k16.row.col.f32.bf16.bf16.f32 "
                    "{%0,%1,%2,%3}, {%4,%5,%6,%7}, {%8,%9}, {%0,%1,%2,%3};"
                    : "+f"(acc[im][in_][0]), "+f"(acc[im][in_][1]),
                      "+f"(acc[im][in_][2]), "+f"(acc[im][in_][3])
                    : "r"(af[im][0]), "r"(af[im][1]),
                      "r"(af[im][2]), "r"(af[im][3]),
                      "r"(bf[in_][0]), "r"(bf[in_][1]));
            }

        if (hasNext) {
            store_smem((it + 1) & 1);
            __syncthreads();
        }
    }

#pragma unroll
    for (int im = 0; im < 4; im++) {
        int r0 = bm + wm * 64 + im * 16 + gid;
        int r1 = r0 + 8;
#pragma unroll
        for (int in_ = 0; in_ < 4; in_++) {
            int c = bn + wn * 32 + in_ * 8 + 2 * tig;
            if (r0 < M)
                *(unsigned short*)(Cout + (size_t)r0 * N + c) =
                    float2_to_fp8x2(acc[im][in_][0], acc[im][in_][1]);
            if (r1 < M)
                *(unsigned short*)(Cout + (size_t)r1 * N + c) =
                    float2_to_fp8x2(acc[im][in_][2], acc[im][in_][3]);
        }
    }
}

// ---------------- CSR gather aggregation (fp8 in) ---------------------------
// warp per node, 2-edge unroll; lane owns 8 channels; writes bf16 a1.
__global__ void __launch_bounds__(256) k_gather256(const __nv_fp8_storage_t* __restrict__ h,
                                                   const float* __restrict__ bias,
                                                   __nv_bfloat16* __restrict__ out) {
    const int node = (blockIdx.x * blockDim.x + threadIdx.x) >> 5;
    const int lane = threadIdx.x & 31;
    if (node >= N_NODES) return;

    float acc[8];
#pragma unroll
    for (int i = 0; i < 8; i++) acc[i] = 0.f;

#define ACC256(q, w) { \
        float2 f0 = fp8x2_to_float2((unsigned short)((q).x & 0xFFFF)); \
        float2 f1 = fp8x2_to_float2((unsigned short)((q).x >> 16)); \
        float2 f2 = fp8x2_to_float2((unsigned short)((q).y & 0xFFFF)); \
        float2 f3 = fp8x2_to_float2((unsigned short)((q).y >> 16)); \
        acc[0] += f0.x * (w); acc[1] += f0.y * (w); \
        acc[2] += f1.x * (w); acc[3] += f1.y * (w); \
        acc[4] += f2.x * (w); acc[5] += f2.y * (w); \
        acc[6] += f3.x * (w); acc[7] += f3.y * (w); }

    const int e0 = g_off[node];
    const int e1 = g_off[node + 1];
    int e = e0;
    for (; e + 2 <= e1; e += 2) {
        int s0 = g_csr[e];
        int s1 = g_csr[e + 1];
        float w0 = g_dinv[s0];
        float w1 = g_dinv[s1];
        uint2 q0 = ((const uint2*)(h + (size_t)s0 * C1))[lane];
        uint2 q1 = ((const uint2*)(h + (size_t)s1 * C1))[lane];
        ACC256(q0, w0)
        ACC256(q1, w1)
    }
    if (e < e1) {
        int s = g_csr[e];
        float w = g_dinv[s];
        uint2 q = ((const uint2*)(h + (size_t)s * C1))[lane];
        ACC256(q, w)
    }

    float dd = g_dinv[node];
    uint2 qs = ((const uint2*)(h + (size_t)node * C1))[lane];
    float2 f0 = fp8x2_to_float2((unsigned short)(qs.x & 0xFFFF));
    float2 f1 = fp8x2_to_float2((unsigned short)(qs.x >> 16));
    float2 f2 = fp8x2_to_float2((unsigned short)(qs.y & 0xFFFF));
    float2 f3 = fp8x2_to_float2((unsigned short)(qs.y >> 16));
    float sf[8] = {f0.x, f0.y, f1.x, f1.y, f2.x, f2.y, f3.x, f3.y};
#undef ACC256

    float4 b0 = ((const float4*)bias)[lane * 2 + 0];
    float4 b1 = ((const float4*)bias)[lane * 2 + 1];
    float bb[8] = {b0.x, b0.y, b0.z, b0.w, b1.x, b1.y, b1.z, b1.w};

    float r[8];
#pragma unroll
    for (int i = 0; i < 8; i++)
        r[i] = fmaxf((acc[i] + sf[i] * dd) * dd + bb[i], 0.f);

    // bf16 pack: lane owns channels 8*lane .. 8*lane+7 = 4 adjacent bf16 pairs
    uint4 o;
    o.x = pack_bf16(r[0], r[1]);
    o.y = pack_bf16(r[2], r[3]);
    o.z = pack_bf16(r[4], r[5]);
    o.w = pack_bf16(r[6], r[7]);
    ((uint4*)(out + (size_t)node * C1))[lane] = o;
}

// warp per node, 4-edge unroll; lane owns 4 channels (uint = 4 fp8).
// FUSED layer-3 GEMM: h3[node] = relu-agg row . W3 via warp reduction.
__global__ void __launch_bounds__(256) k_gather128_gemm3(
        const __nv_fp8_storage_t* __restrict__ h,
        const float* __restrict__ bias,
        const float* __restrict__ W3,
        float* __restrict__ h3out) {
    const int node = (blockIdx.x * blockDim.x + threadIdx.x) >> 5;
    const int lane = threadIdx.x & 31;
    if (node >= N_NODES) return;

    float acc[4] = {0.f, 0.f, 0.f, 0.f};

#define ACC128(q, w) { \
        float2 fa = fp8x2_to_float2((unsigned short)((q) & 0xFFFF)); \
        float2 fb = fp8x2_to_float2((unsigned short)((q) >> 16)); \
        acc[0] += fa.x * (w); acc[1] += fa.y * (w); \
        acc[2] += fb.x * (w); acc[3] += fb.y * (w); }

    const int e0 = g_off[node];
    const int e1 = g_off[node + 1];
    int e = e0;
    for (; e + 4 <= e1; e += 4) {
        int s0 = g_csr[e], s1 = g_csr[e + 1], s2 = g_csr[e + 2], s3 = g_csr[e + 3];
        float w0 = g_dinv[s0], w1 = g_dinv[s1], w2 = g_dinv[s2], w3 = g_dinv[s3];
        unsigned q0 = ((const unsigned*)(h + (size_t)s0 * C2))[lane];
        unsigned q1 = ((const unsigned*)(h + (size_t)s1 * C2))[lane];
        unsigned q2 = ((const unsigned*)(h + (size_t)s2 * C2))[lane];
        unsigned q3 = ((const unsigned*)(h + (size_t)s3 * C2))[lane];
        ACC128(q0, w0) ACC128(q1, w1) ACC128(q2, w2) ACC128(q3, w3)
    }
    for (; e < e1; e++) {
        int s = g_csr[e];
        float w = g_dinv[s];
        unsigned q = ((const unsigned*)(h + (size_t)s * C2))[lane];
        ACC128(q, w)
    }

    float dd = g_dinv[node];
    unsigned qs = ((const unsigned*)(h + (size_t)node * C2))[lane];
    float2 f0 = fp8x2_to_float2((unsigned short)(qs & 0xFFFF));
    float2 f1 = fp8x2_to_float2((unsigned short)(qs >> 16));
    float sf[4] = {f0.x, f0.y, f1.x, f1.y};
#undef ACC128

    float4 b = ((const float4*)bias)[lane];
    float bb[4] = {b.x, b.y, b.z, b.w};

    float r[4];
#pragma unroll
    for (int i = 0; i < 4; i++)
        r[i] = fmaxf((acc[i] + sf[i] * dd) * dd + bb[i], 0.f);

    float h30 = 0.f, h31 = 0.f;
#pragma unroll
    for (int i = 0; i < 4; i++) {
        float2 wv = ((const float2*)W3)[lane * 4 + i];
        h30 += r[i] * wv.x;
        h31 += r[i] * wv.y;
    }
#pragma unroll
    for (int o = 16; o > 0; o >>= 1) {
        h30 += __shfl_down_sync(0xffffffffu, h30, o);
        h31 += __shfl_down_sync(0xffffffffu, h31, o);
    }
    if (lane == 0)
        ((float2*)h3out)[node] = make_float2(h30, h31);
}

__global__ void __launch_bounds__(256) k_gather2_sig(const float* __restrict__ h,
                                                     const float* __restrict__ bias,
                                                     float* __restrict__ out) {
    const int node = (blockIdx.x * blockDim.x + threadIdx.x) >> 5;
    const int lane = threadIdx.x & 31;
    if (node >= N_NODES) return;

    float a0 = 0.f, a1 = 0.f;
    const int e0 = g_off[node];
    const int e1 = g_off[node + 1];
    for (int e = e0 + lane; e < e1; e += 32) {
        int s = g_csr[e];
        float w = g_dinv[s];
        float2 f = ((const float2*)h)[s];
        a0 += f.x * w;
        a1 += f.y * w;
    }
#pragma unroll
    for (int o = 16; o > 0; o >>= 1) {
        a0 += __shfl_down_sync(0xffffffffu, a0, o);
        a1 += __shfl_down_sync(0xffffffffu, a1, o);
    }
    if (lane == 0) {
        float dd = g_dinv[node];
        float2 f = ((const float2*)h)[node];
        float r0 = (a0 + f.x * dd) * dd + bias[0];
        float r1 = (a1 + f.y * dd) * dd + bias[1];
        float2 o2;
        o2.x = 1.0f / (1.0f + expf(-r0));
        o2.y = 1.0f / (1.0f + expf(-r1));
        ((float2*)out)[node] = o2;
    }
}

// ---------------- launch ----------------------------------------------------
extern "C" void kernel_launch(void* const* d_in, const int* in_sizes, int n_in,
                              void* d_out, int out_size) {
    const float* x  = (const float*)d_in[0];
    const int*   ei = (const int*)d_in[1];
    const float* W1 = (const float*)d_in[2];
    const float* b1 = (const float*)d_in[3];
    const float* W2 = (const float*)d_in[4];
    const float* b2 = (const float*)d_in[5];
    const float* W3 = (const float*)d_in[6];
    const float* b3 = (const float*)d_in[7];
    float* out = (float*)d_out;

    const int* src = ei;
    const int* dst = ei + N_EDGES;

    __nv_fp8_storage_t* h1; cudaGetSymbolAddress((void**)&h1, g_h1);
    __nv_bfloat16* a1;      cudaGetSymbolAddress((void**)&a1, g_a1);
    __nv_fp8_storage_t* h2; cudaGetSymbolAddress((void**)&h2, g_h2);
    float* h3;              cudaGetSymbolAddress((void**)&h3, g_h3);

    // one-time host resources (created on the uncaptured correctness call)
    static cudaStream_t s2 = nullptr;
    static cudaEvent_t ev_fork = nullptr, ev_join = nullptr;
    static bool init_done = false;
    if (!init_done) {
        cudaStreamCreateWithFlags(&s2, cudaStreamNonBlocking);
        cudaEventCreateWithFlags(&ev_fork, cudaEventDisableTiming);
        cudaEventCreateWithFlags(&ev_join, cudaEventDisableTiming);
        init_done = true;
    }

    const int T = 256;

    // ---- fork: CSR build on s2, GEMM1 on main stream (independent work)
    cudaEventRecord(ev_fork, 0);
    cudaStreamWaitEvent(s2, ev_fork, 0);

    k_zero_cnt<<<(N_NODES + T - 1) / T, T, 0, s2>>>();
    k_count<<<(N_EDGES + T - 1) / T, T, 0, s2>>>(dst);
    k_scan<<<1, SCAN_T, 0, s2>>>();
    k_fill<<<(N_EDGES + T - 1) / T, T, 0, s2>>>(src, dst);
    cudaEventRecord(ev_join, s2);

    // ---- layer 1 GEMM (BN=256: x read from DRAM exactly once), fp8 out
    {
        dim3 grid(1, (N_NODES + 127) / 128);
        bf16_gemm_n256<<<grid, 512>>>(x, W1, h1, N_NODES, C_IN);
    }

    // ---- join: gather needs both CSR and h1
    cudaStreamWaitEvent(0, ev_join, 0);

    k_gather256<<<(N_NODES * 32 + T - 1) / T, T>>>(h1, b1, a1);

    // ---- layer 2 GEMM (A already bf16 packed), fp8 out
    {
        dim3 grid(1, (N_NODES + 127) / 128);
        bf16_gemm_abf16<<<grid, 256>>>(a1, W2, h2, N_NODES, C1, C2);
    }

    // ---- layer 2 aggregation + fused layer-3 GEMM
    k_gather128_gemm3<<<(N_NODES * 32 + T - 1) / T, T>>>(h2, b2, W3, h3);

    // ---- layer 3 aggregation + sigmoid
    k_gather2_sig<<<(N_NODES * 32 + T - 1) / T, T>>>(h3, b3, out);
}

// round 16
// speedup vs baseline: 1.0823x; 1.0823x over previous
#include <cuda_runtime.h>
#include <cuda_bf16.h>
#include <cuda_fp8.h>
#include <stdint.h>
#include <math.h>

#define N_NODES 50000
#define N_EDGES 800000
#define C_IN    768
#define C1      256
#define C2      128
#define C3      2

#define SCAN_T  1024
#define SCAN_CH ((N_NODES + SCAN_T - 1) / SCAN_T)   // 49

#define W1_SCALE     64.0f
#define W1_SCALE_INV (1.0f / 64.0f)

// ---------------- scratch (device globals; no allocation allowed) ----------
__device__ float g_dinv[N_NODES];
__device__ int   g_cnt[N_NODES];            // counts, then write cursor
__device__ int   g_off[N_NODES + 1];
__device__ int   g_csr[N_EDGES];            // src ids grouped by dst
__device__ __nv_fp8_storage_t g_h1[(size_t)N_NODES * C1];   // x@W1 (e4m3)
__device__ __nv_bfloat16 g_a1[(size_t)N_NODES * C1];        // relu(A h1 + b1) (bf16)
__device__ __nv_fp8_storage_t g_h2[(size_t)N_NODES * C2];   // a1@W2 (e4m3)
__device__ float g_h3[(size_t)N_NODES * C3];

// ---------------- fp8 helpers -----------------------------------------------
__device__ __forceinline__ float2 fp8x2_to_float2(unsigned short v) {
    __half2_raw hr = __nv_cvt_fp8x2_to_halfraw2((__nv_fp8x2_storage_t)v, __NV_E4M3);
    return __half22float2(*(__half2*)&hr);
}

__device__ __forceinline__ unsigned short float2_to_fp8x2(float a, float b) {
    return (unsigned short)__nv_cvt_float2_to_fp8x2(make_float2(a, b),
                                                    __NV_SATFINITE, __NV_E4M3);
}

__device__ __forceinline__ unsigned pack_fp8x4(float a, float b, float c, float d) {
    unsigned lo = float2_to_fp8x2(a, b);
    unsigned hi = float2_to_fp8x2(c, d);
    return lo | (hi << 16);
}

// ---------------- CSR build -------------------------------------------------
__global__ void k_zero_cnt() {
    int i = blockIdx.x * blockDim.x + threadIdx.x;
    if (i < N_NODES) g_cnt[i] = 0;
}

__global__ void k_count(const int* __restrict__ dst) {
    int e = blockIdx.x * blockDim.x + threadIdx.x;
    if (e < N_EDGES) atomicAdd(&g_cnt[dst[e]], 1);
}

__global__ void __launch_bounds__(SCAN_T) k_scan() {
    __shared__ int s_part[SCAN_T];
    const int t = threadIdx.x;
    const int start = t * SCAN_CH;
    const int end   = min(start + SCAN_CH, N_NODES);

    int sum = 0;
    for (int i = start; i < end; i++) {
        int c = g_cnt[i];
        sum += c;
        g_dinv[i] = rsqrtf((float)(c + 1));   // +1 self loop
    }
    s_part[t] = sum;
    __syncthreads();
    for (int ofs = 1; ofs < SCAN_T; ofs <<= 1) {
        int v = 0;
        if (t >= ofs) v = s_part[t - ofs];
        __syncthreads();
        if (t >= ofs) s_part[t] += v;
        __syncthreads();
    }
    int run = (t == 0) ? 0 : s_part[t - 1];
    for (int i = start; i < end; i++) {
        int c = g_cnt[i];
        g_off[i] = run;
        g_cnt[i] = run;       // cursor for k_fill
        run += c;
    }
    if (start < N_NODES && end == N_NODES) g_off[N_NODES] = run;
}

__global__ void k_fill(const int* __restrict__ src, const int* __restrict__ dst) {
    int e = blockIdx.x * blockDim.x + threadIdx.x;
    if (e < N_EDGES) {
        int pos = atomicAdd(&g_cnt[dst[e]], 1);
        g_csr[pos] = src[e];
    }
}

// ---------------- bf16 pack helper ------------------------------------------
__device__ __forceinline__ unsigned pack_bf16(float lo, float hi) {
    __nv_bfloat162 v = __floats2bfloat162_rn(lo, hi);
    return *(unsigned*)&v;
}

// ===== FP8 GEMM layer 1: BM=128, BN=256, 512 thr, m16n8k32 e4m3 =============
// C = A[M,K](fp32->e4m3) @ (B[K,N](fp32)*W1_SCALE -> e4m3), acc fp32,
// epilogue * W1_SCALE_INV, out e4m3.
// Smem: k-quad packed uint32 (4 consecutive k fp8).
//   As_q[m][12] (8 quads + 4 pad)  frag A: bank perm 12*gid+tig  (conflict-free)
//   Bs_q[kq][264]                  frag B: bank perm 8*tig+gid   (conflict-free)
__global__ void __launch_bounds__(512) fp8_gemm_n256(const float* __restrict__ A,
                                                     const float* __restrict__ B,
                                                     __nv_fp8_storage_t* __restrict__ Cout,
                                                     int M, int K) {
    const int N = 256;
    __shared__ unsigned As_q[2][128][12];
    __shared__ unsigned Bs_q[2][8][264];

    const int tid  = threadIdx.x;
    const int warp = tid >> 5;
    const int lane = tid & 31;
    const int gid  = lane >> 2;
    const int tig  = lane & 3;
    const int wm   = warp & 1;       // 2 m-warps
    const int wn   = warp >> 1;      // 8 n-warps
    const int bm   = blockIdx.y * 128;

    // A staging: thread t -> row = t>>2, k-oct = (t&3) (8 floats = 2 quads)
    const int am  = tid >> 2;
    const int ak8 = tid & 3;
    // B staging: thread t -> k-quad = t>>6 (0..7), n4 = (t&63)*4
    const int bkq = tid >> 6;
    const int bn4 = (tid & 63) * 4;

    float acc[4][4][4];
#pragma unroll
    for (int i = 0; i < 4; i++)
#pragma unroll
        for (int j = 0; j < 4; j++)
#pragma unroll
            for (int q = 0; q < 4; q++) acc[i][j][q] = 0.0f;

    const int nIter = K / 32;   // 24
    float4 la0, la1;            // A: 8 floats
    float4 lb[4];               // B: 4 rows x 4 cols

    auto load_regs = [&](int it) {
        int k0 = it * 32;
        if (bm + am < M) {
            const float* ap = A + (size_t)(bm + am) * K + k0 + ak8 * 8;
            la0 = *(const float4*)ap;
            la1 = *(const float4*)(ap + 4);
        } else {
            la0 = make_float4(0.f, 0.f, 0.f, 0.f); la1 = la0;
        }
        const float* bp = B + (size_t)(k0 + bkq * 4) * N + bn4;
#pragma unroll
        for (int r = 0; r < 4; r++)
            lb[r] = *(const float4*)(bp + (size_t)r * N);
    };

    auto store_smem = [&](int buf) {
        // A: 2 k-quads
        As_q[buf][am][ak8 * 2 + 0] = pack_fp8x4(la0.x, la0.y, la0.z, la0.w);
        As_q[buf][am][ak8 * 2 + 1] = pack_fp8x4(la1.x, la1.y, la1.z, la1.w);
        // B: 4 n-columns, each packs k rows 0..3 of this quad (scaled)
        uint4 o;
        o.x = pack_fp8x4(lb[0].x * W1_SCALE, lb[1].x * W1_SCALE,
                         lb[2].x * W1_SCALE, lb[3].x * W1_SCALE);
        o.y = pack_fp8x4(lb[0].y * W1_SCALE, lb[1].y * W1_SCALE,
                         lb[2].y * W1_SCALE, lb[3].y * W1_SCALE);
        o.z = pack_fp8x4(lb[0].z * W1_SCALE, lb[1].z * W1_SCALE,
                         lb[2].z * W1_SCALE, lb[3].z * W1_SCALE);
        o.w = pack_fp8x4(lb[0].w * W1_SCALE, lb[1].w * W1_SCALE,
                         lb[2].w * W1_SCALE, lb[3].w * W1_SCALE);
        *(uint4*)&Bs_q[buf][bkq][bn4] = o;
    };

    load_regs(0);
    store_smem(0);
    __syncthreads();

    for (int it = 0; it < nIter; it++) {
        int buf = it & 1;
        bool hasNext = (it + 1) < nIter;
        if (hasNext) load_regs(it + 1);

        unsigned af[4][4], bf[4][2];
#pragma unroll
        for (int im = 0; im < 4; im++) {
            int m = wm * 64 + im * 16 + gid;
            af[im][0] = As_q[buf][m][tig];          // k = 4*tig
            af[im][1] = As_q[buf][m + 8][tig];
            af[im][2] = As_q[buf][m][tig + 4];      // k = 16 + 4*tig
            af[im][3] = As_q[buf][m + 8][tig + 4];
        }
#pragma unroll
        for (int in_ = 0; in_ < 4; in_++) {
            int n = wn * 32 + in_ * 8 + gid;
            bf[in_][0] = Bs_q[buf][tig][n];         // k = 4*tig
            bf[in_][1] = Bs_q[buf][tig + 4][n];     // k = 16 + 4*tig
        }
#pragma unroll
        for (int im = 0; im < 4; im++)
#pragma unroll
            for (int in_ = 0; in_ < 4; in_++) {
                asm volatile(
                    "mma.sync.aligned.m16n8k32.row.col.f32.e4m3.e4m3.f32 "
                    "{%0,%1,%2,%3}, {%4,%5,%6,%7}, {%8,%9}, {%0,%1,%2,%3};"
                    : "+f"(acc[im][in_][0]), "+f"(acc[im][in_][1]),
                      "+f"(acc[im][in_][2]), "+f"(acc[im][in_][3])
                    : "r"(af[im][0]), "r"(af[im][1]),
                      "r"(af[im][2]), "r"(af[im][3]),
                      "r"(bf[in_][0]), "r"(bf[in_][1]));
            }

        if (hasNext) {
            store_smem((it + 1) & 1);
            __syncthreads();
        }
    }

#pragma unroll
    for (int im = 0; im < 4; im++) {
        int r0 = bm + wm * 64 + im * 16 + gid;
        int r1 = r0 + 8;
#pragma unroll
        for (int in_ = 0; in_ < 4; in_++) {
            int c = wn * 32 + in_ * 8 + 2 * tig;
            if (r0 < M)
                *(unsigned short*)(Cout + (size_t)r0 * N + c) =
                    float2_to_fp8x2(acc[im][in_][0] * W1_SCALE_INV,
                                    acc[im][in_][1] * W1_SCALE_INV);
            if (r1 < M)
                *(unsigned short*)(Cout + (size_t)r1 * N + c) =
                    float2_to_fp8x2(acc[im][in_][2] * W1_SCALE_INV,
                                    acc[im][in_][3] * W1_SCALE_INV);
        }
    }
}

// ===== BF16 GEMM layer 2: BM=128, BN=128, A bf16 k-pair packed ==============
__global__ void __launch_bounds__(256) bf16_gemm_abf16(const __nv_bfloat16* __restrict__ A,
                                                       const float* __restrict__ B,
                                                       __nv_fp8_storage_t* __restrict__ Cout,
                                                       int M, int K, int N) {
    __shared__ unsigned As_p[2][128][12];
    __shared__ unsigned Bs_p[2][8][136];

    const int tid  = threadIdx.x;
    const int warp = tid >> 5;
    const int lane = tid & 31;
    const int gid  = lane >> 2;
    const int tig  = lane & 3;
    const int wm   = warp & 1;
    const int wn   = warp >> 1;
    const int bm   = blockIdx.y * 128;
    const int bn   = blockIdx.x * 128;

    const int am = tid >> 1;
    const int akh = tid & 1;
    const int bw = warp;
    const int bn4 = lane * 4;

    float acc[4][4][4];
#pragma unroll
    for (int i = 0; i < 4; i++)
#pragma unroll
        for (int j = 0; j < 4; j++)
#pragma unroll
            for (int q = 0; q < 4; q++) acc[i][j][q] = 0.0f;

    const int nIter = K / 16;
    uint4 laq;
    float4 lb0, lb1;

    auto load_regs = [&](int it) {
        if (bm + am < M)
            laq = ((const uint4*)(A + (size_t)(bm + am) * K))[it * 2 + akh];
        else
            laq = make_uint4(0u, 0u, 0u, 0u);
        int k0 = it * 16;
        const float* bp = B + (size_t)(k0 + 2 * bw) * N + bn + bn4;
        lb0 = *(const float4*)bp;
        lb1 = *(const float4*)(bp + N);
    };

    auto store_smem = [&](int buf) {
        *(uint4*)&As_p[buf][am][akh * 4] = laq;
        unsigned ub0 = pack_bf16(lb0.x, lb1.x);
        unsigned ub1 = pack_bf16(lb0.y, lb1.y);
        unsigned ub2 = pack_bf16(lb0.z, lb1.z);
        unsigned ub3 = pack_bf16(lb0.w, lb1.w);
        *(uint4*)&Bs_p[buf][bw][bn4] = make_uint4(ub0, ub1, ub2, ub3);
    };

    load_regs(0);
    store_smem(0);
    __syncthreads();

    for (int it = 0; it < nIter; it++) {
        int buf = it & 1;
        bool hasNext = (it + 1) < nIter;
        if (hasNext) load_regs(it + 1);

        unsigned af[4][4], bf[4][2];
#pragma unroll
        for (int im = 0; im < 4; im++) {
            int m = wm * 64 + im * 16 + gid;
            af[im][0] = As_p[buf][m][tig];
            af[im][1] = As_p[buf][m + 8][tig];
            af[im][2] = As_p[buf][m][tig + 4];
            af[im][3] = As_p[buf][m + 8][tig + 4];
        }
#pragma unroll
        for (int in_ = 0; in_ < 4; in_++) {
            int n = wn * 32 + in_ * 8 + gid;
            bf[in_][0] = Bs_p[buf][tig][n];
            bf[in_][1] = Bs_p[buf][tig + 4][n];
        }
#pragma unroll
        for (int im = 0; im < 4; im++)
#pragma unroll
            for (int in_ = 0; in_ < 4; in_++) {
                asm volatile(
                    "mma.sync.aligned.m16n8k16.row.col.f32.bf16.bf16.f32 "
                    "{%0,%1,%2,%3}, {%4,%5,%6,%7}, {%8,%9}, {%0,%1,%2,%3};"
                    : "+f"(acc[im][in_][0]), "+f"(acc[im][in_][1]),
                      "+f"(acc[im][in_][2]), "+f"(acc[im][in_][3])
                    : "r"(af[im][0]), "r"(af[im][1]),
                      "r"(af[im][2]), "r"(af[im][3]),
                      "r"(bf[in_][0]), "r"(bf[in_][1]));
            }

        if (hasNext) {
            store_smem((it + 1) & 1);
            __syncthreads();
        }
    }

#pragma unroll
    for (int im = 0; im < 4; im++) {
        int r0 = bm + wm * 64 + im * 16 + gid;
        int r1 = r0 + 8;
#pragma unroll
        for (int in_ = 0; in_ < 4; in_++) {
            int c = bn + wn * 32 + in_ * 8 + 2 * tig;
            if (r0 < M)
                *(unsigned short*)(Cout + (size_t)r0 * N + c) =
                    float2_to_fp8x2(acc[im][in_][0], acc[im][in_][1]);
            if (r1 < M)
                *(unsigned short*)(Cout + (size_t)r1 * N + c) =
                    float2_to_fp8x2(acc[im][in_][2], acc[im][in_][3]);
        }
    }
}

// ---------------- CSR gather aggregation (fp8 in) ---------------------------
// warp per node, 2-edge unroll; lane owns 8 channels; writes bf16 a1.
__global__ void __launch_bounds__(256) k_gather256(const __nv_fp8_storage_t* __restrict__ h,
                                                   const float* __restrict__ bias,
                                                   __nv_bfloat16* __restrict__ out) {
    const int node = (blockIdx.x * blockDim.x + threadIdx.x) >> 5;
    const int lane = threadIdx.x & 31;
    if (node >= N_NODES) return;

    float acc[8];
#pragma unroll
    for (int i = 0; i < 8; i++) acc[i] = 0.f;

#define ACC256(q, w) { \
        float2 f0 = fp8x2_to_float2((unsigned short)((q).x & 0xFFFF)); \
        float2 f1 = fp8x2_to_float2((unsigned short)((q).x >> 16)); \
        float2 f2 = fp8x2_to_float2((unsigned short)((q).y & 0xFFFF)); \
        float2 f3 = fp8x2_to_float2((unsigned short)((q).y >> 16)); \
        acc[0] += f0.x * (w); acc[1] += f0.y * (w); \
        acc[2] += f1.x * (w); acc[3] += f1.y * (w); \
        acc[4] += f2.x * (w); acc[5] += f2.y * (w); \
        acc[6] += f3.x * (w); acc[7] += f3.y * (w); }

    const int e0 = g_off[node];
    const int e1 = g_off[node + 1];
    int e = e0;
    for (; e + 2 <= e1; e += 2) {
        int s0 = g_csr[e];
        int s1 = g_csr[e + 1];
        float w0 = g_dinv[s0];
        float w1 = g_dinv[s1];
        uint2 q0 = ((const uint2*)(h + (size_t)s0 * C1))[lane];
        uint2 q1 = ((const uint2*)(h + (size_t)s1 * C1))[lane];
        ACC256(q0, w0)
        ACC256(q1, w1)
    }
    if (e < e1) {
        int s = g_csr[e];
        float w = g_dinv[s];
        uint2 q = ((const uint2*)(h + (size_t)s * C1))[lane];
        ACC256(q, w)
    }

    float dd = g_dinv[node];
    uint2 qs = ((const uint2*)(h + (size_t)node * C1))[lane];
    float2 f0 = fp8x2_to_float2((unsigned short)(qs.x & 0xFFFF));
    float2 f1 = fp8x2_to_float2((unsigned short)(qs.x >> 16));
    float2 f2 = fp8x2_to_float2((unsigned short)(qs.y & 0xFFFF));
    float2 f3 = fp8x2_to_float2((unsigned short)(qs.y >> 16));
    float sf[8] = {f0.x, f0.y, f1.x, f1.y, f2.x, f2.y, f3.x, f3.y};
#undef ACC256

    float4 b0 = ((const float4*)bias)[lane * 2 + 0];
    float4 b1 = ((const float4*)bias)[lane * 2 + 1];
    float bb[8] = {b0.x, b0.y, b0.z, b0.w, b1.x, b1.y, b1.z, b1.w};

    float r[8];
#pragma unroll
    for (int i = 0; i < 8; i++)
        r[i] = fmaxf((acc[i] + sf[i] * dd) * dd + bb[i], 0.f);

    uint4 o;
    o.x = pack_bf16(r[0], r[1]);
    o.y = pack_bf16(r[2], r[3]);
    o.z = pack_bf16(r[4], r[5]);
    o.w = pack_bf16(r[6], r[7]);
    ((uint4*)(out + (size_t)node * C1))[lane] = o;
}

// warp per node, 4-edge unroll; lane owns 4 channels (uint = 4 fp8).
// FUSED layer-3 GEMM: h3[node] = relu-agg row . W3 via warp reduction.
__global__ void __launch_bounds__(256) k_gather128_gemm3(
        const __nv_fp8_storage_t* __restrict__ h,
        const float* __restrict__ bias,
        const float* __restrict__ W3,
        float* __restrict__ h3out) {
    const int node = (blockIdx.x * blockDim.x + threadIdx.x) >> 5;
    const int lane = threadIdx.x & 31;
    if (node >= N_NODES) return;

    float acc[4] = {0.f, 0.f, 0.f, 0.f};

#define ACC128(q, w) { \
        float2 fa = fp8x2_to_float2((unsigned short)((q) & 0xFFFF)); \
        float2 fb = fp8x2_to_float2((unsigned short)((q) >> 16)); \
        acc[0] += fa.x * (w); acc[1] += fa.y * (w); \
        acc[2] += fb.x * (w); acc[3] += fb.y * (w); }

    const int e0 = g_off[node];
    const int e1 = g_off[node + 1];
    int e = e0;
    for (; e + 4 <= e1; e += 4) {
        int s0 = g_csr[e], s1 = g_csr[e + 1], s2 = g_csr[e + 2], s3 = g_csr[e + 3];
        float w0 = g_dinv[s0], w1 = g_dinv[s1], w2 = g_dinv[s2], w3 = g_dinv[s3];
        unsigned q0 = ((const unsigned*)(h + (size_t)s0 * C2))[lane];
        unsigned q1 = ((const unsigned*)(h + (size_t)s1 * C2))[lane];
        unsigned q2 = ((const unsigned*)(h + (size_t)s2 * C2))[lane];
        unsigned q3 = ((const unsigned*)(h + (size_t)s3 * C2))[lane];
        ACC128(q0, w0) ACC128(q1, w1) ACC128(q2, w2) ACC128(q3, w3)
    }
    for (; e < e1; e++) {
        int s = g_csr[e];
        float w = g_dinv[s];
        unsigned q = ((const unsigned*)(h + (size_t)s * C2))[lane];
        ACC128(q, w)
    }

    float dd = g_dinv[node];
    unsigned qs = ((const unsigned*)(h + (size_t)node * C2))[lane];
    float2 f0 = fp8x2_to_float2((unsigned short)(qs & 0xFFFF));
    float2 f1 = fp8x2_to_float2((unsigned short)(qs >> 16));
    float sf[4] = {f0.x, f0.y, f1.x, f1.y};
#undef ACC128

    float4 b = ((const float4*)bias)[lane];
    float bb[4] = {b.x, b.y, b.z, b.w};

    float r[4];
#pragma unroll
    for (int i = 0; i < 4; i++)
        r[i] = fmaxf((acc[i] + sf[i] * dd) * dd + bb[i], 0.f);

    float h30 = 0.f, h31 = 0.f;
#pragma unroll
    for (int i = 0; i < 4; i++) {
        float2 wv = ((const float2*)W3)[lane * 4 + i];
        h30 += r[i] * wv.x;
        h31 += r[i] * wv.y;
    }
#pragma unroll
    for (int o = 16; o > 0; o >>= 1) {
        h30 += __shfl_down_sync(0xffffffffu, h30, o);
        h31 += __shfl_down_sync(0xffffffffu, h31, o);
    }
    if (lane == 0)
        ((float2*)h3out)[node] = make_float2(h30, h31);
}

__global__ void __launch_bounds__(256) k_gather2_sig(const float* __restrict__ h,
                                                     const float* __restrict__ bias,
                                                     float* __restrict__ out) {
    const int node = (blockIdx.x * blockDim.x + threadIdx.x) >> 5;
    const int lane = threadIdx.x & 31;
    if (node >= N_NODES) return;

    float a0 = 0.f, a1 = 0.f;
    const int e0 = g_off[node];
    const int e1 = g_off[node + 1];
    for (int e = e0 + lane; e < e1; e += 32) {
        int s = g_csr[e];
        float w = g_dinv[s];
        float2 f = ((const float2*)h)[s];
        a0 += f.x * w;
        a1 += f.y * w;
    }
#pragma unroll
    for (int o = 16; o > 0; o >>= 1) {
        a0 += __shfl_down_sync(0xffffffffu, a0, o);
        a1 += __shfl_down_sync(0xffffffffu, a1, o);
    }
    if (lane == 0) {
        float dd = g_dinv[node];
        float2 f = ((const float2*)h)[node];
        float r0 = (a0 + f.x * dd) * dd + bias[0];
        float r1 = (a1 + f.y * dd) * dd + bias[1];
        float2 o2;
        o2.x = 1.0f / (1.0f + expf(-r0));
        o2.y = 1.0f / (1.0f + expf(-r1));
        ((float2*)out)[node] = o2;
    }
}

// ---------------- launch ----------------------------------------------------
extern "C" void kernel_launch(void* const* d_in, const int* in_sizes, int n_in,
                              void* d_out, int out_size) {
    const float* x  = (const float*)d_in[0];
    const int*   ei = (const int*)d_in[1];
    const float* W1 = (const float*)d_in[2];
    const float* b1 = (const float*)d_in[3];
    const float* W2 = (const float*)d_in[4];
    const float* b2 = (const float*)d_in[5];
    const float* W3 = (const float*)d_in[6];
    const float* b3 = (const float*)d_in[7];
    float* out = (float*)d_out;

    const int* src = ei;
    const int* dst = ei + N_EDGES;

    __nv_fp8_storage_t* h1; cudaGetSymbolAddress((void**)&h1, g_h1);
    __nv_bfloat16* a1;      cudaGetSymbolAddress((void**)&a1, g_a1);
    __nv_fp8_storage_t* h2; cudaGetSymbolAddress((void**)&h2, g_h2);
    float* h3;              cudaGetSymbolAddress((void**)&h3, g_h3);

    // one-time host resources (created on the uncaptured correctness call)
    static cudaStream_t s2 = nullptr;
    static cudaEvent_t ev_fork = nullptr, ev_join = nullptr;
    static bool init_done = false;
    if (!init_done) {
        cudaStreamCreateWithFlags(&s2, cudaStreamNonBlocking);
        cudaEventCreateWithFlags(&ev_fork, cudaEventDisableTiming);
        cudaEventCreateWithFlags(&ev_join, cudaEventDisableTiming);
        init_done = true;
    }

    const int T = 256;

    // ---- fork: CSR build on s2, GEMM1 on main stream (independent work)
    cudaEventRecord(ev_fork, 0);
    cudaStreamWaitEvent(s2, ev_fork, 0);

    k_zero_cnt<<<(N_NODES + T - 1) / T, T, 0, s2>>>();
    k_count<<<(N_EDGES + T - 1) / T, T, 0, s2>>>(dst);
    k_scan<<<1, SCAN_T, 0, s2>>>();
    k_fill<<<(N_EDGES + T - 1) / T, T, 0, s2>>>(src, dst);
    cudaEventRecord(ev_join, s2);

    // ---- layer 1 GEMM: fp8 tensor cores (e4m3 m16n8k32), fp8 out
    {
        dim3 grid(1, (N_NODES + 127) / 128);
        fp8_gemm_n256<<<grid, 512>>>(x, W1, h1, N_NODES, C_IN);
    }

    // ---- join: gather needs both CSR and h1
    cudaStreamWaitEvent(0, ev_join, 0);

    k_gather256<<<(N_NODES * 32 + T - 1) / T, T>>>(h1, b1, a1);

    // ---- layer 2 GEMM (A bf16 packed), fp8 out
    {
        dim3 grid(1, (N_NODES + 127) / 128);
        bf16_gemm_abf16<<<grid, 256>>>(a1, W2, h2, N_NODES, C1, C2);
    }

    // ---- layer 2 aggregation + fused layer-3 GEMM
    k_gather128_gemm3<<<(N_NODES * 32 + T - 1) / T, T>>>(h2, b2, W3, h3);

    // ---- layer 3 aggregation + sigmoid
    k_gather2_sig<<<(N_NODES * 32 + T - 1) / T, T>>>(h3, b3, out);
}

// round 17
// speedup vs baseline: 1.1365x; 1.0501x over previous
#include <cuda_runtime.h>
#include <cuda_bf16.h>
#include <cuda_fp16.h>
#include <cuda_fp8.h>
#include <stdint.h>
#include <math.h>

#define N_NODES 50000
#define N_EDGES 800000
#define C_IN    768
#define C1      256
#define C2      128
#define C3      2

#define SCAN_T  1024
#define SCAN_CH ((N_NODES + SCAN_T - 1) / SCAN_T)   // 49

#define W1_SCALE     64.0f
#define W1_SCALE_INV (1.0f / 64.0f)

// ---------------- scratch (device globals; no allocation allowed) ----------
__device__ float g_dinv[N_NODES];
__device__ int   g_cnt[N_NODES];            // counts, then write cursor
__device__ int   g_off[N_NODES + 1];
__device__ int   g_csr[N_EDGES];            // src ids grouped by dst
__device__ __nv_fp8_storage_t g_h1[(size_t)N_NODES * C1];   // x@W1 (e4m3)
__device__ __nv_bfloat16 g_a1[(size_t)N_NODES * C1];        // relu(A h1 + b1) (bf16)
__device__ __nv_fp8_storage_t g_h2[(size_t)N_NODES * C2];   // a1@W2 (e4m3)
__device__ float g_h3[(size_t)N_NODES * C3];

// ---------------- fp8 helpers -----------------------------------------------
__device__ __forceinline__ __half2 fp8x2_to_half2(unsigned short v) {
    __half2_raw hr = __nv_cvt_fp8x2_to_halfraw2((__nv_fp8x2_storage_t)v, __NV_E4M3);
    return *(__half2*)&hr;
}

__device__ __forceinline__ float2 fp8x2_to_float2(unsigned short v) {
    return __half22float2(fp8x2_to_half2(v));
}

__device__ __forceinline__ unsigned short float2_to_fp8x2(float a, float b) {
    return (unsigned short)__nv_cvt_float2_to_fp8x2(make_float2(a, b),
                                                    __NV_SATFINITE, __NV_E4M3);
}

__device__ __forceinline__ unsigned pack_fp8x4(float a, float b, float c, float d) {
    unsigned lo = float2_to_fp8x2(a, b);
    unsigned hi = float2_to_fp8x2(c, d);
    return lo | (hi << 16);
}

// ---------------- CSR build -------------------------------------------------
__global__ void k_zero_cnt() {
    int i = blockIdx.x * blockDim.x + threadIdx.x;
    if (i < N_NODES) g_cnt[i] = 0;
}

__global__ void k_count(const int* __restrict__ dst) {
    int e = blockIdx.x * blockDim.x + threadIdx.x;
    if (e < N_EDGES) atomicAdd(&g_cnt[dst[e]], 1);
}

__global__ void __launch_bounds__(SCAN_T) k_scan() {
    __shared__ int s_part[SCAN_T];
    const int t = threadIdx.x;
    const int start = t * SCAN_CH;
    const int end   = min(start + SCAN_CH, N_NODES);

    int sum = 0;
    for (int i = start; i < end; i++) {
        int c = g_cnt[i];
        sum += c;
        g_dinv[i] = rsqrtf((float)(c + 1));   // +1 self loop
    }
    s_part[t] = sum;
    __syncthreads();
    for (int ofs = 1; ofs < SCAN_T; ofs <<= 1) {
        int v = 0;
        if (t >= ofs) v = s_part[t - ofs];
        __syncthreads();
        if (t >= ofs) s_part[t] += v;
        __syncthreads();
    }
    int run = (t == 0) ? 0 : s_part[t - 1];
    for (int i = start; i < end; i++) {
        int c = g_cnt[i];
        g_off[i] = run;
        g_cnt[i] = run;       // cursor for k_fill
        run += c;
    }
    if (start < N_NODES && end == N_NODES) g_off[N_NODES] = run;
}

__global__ void k_fill(const int* __restrict__ src, const int* __restrict__ dst) {
    int e = blockIdx.x * blockDim.x + threadIdx.x;
    if (e < N_EDGES) {
        int pos = atomicAdd(&g_cnt[dst[e]], 1);
        g_csr[pos] = src[e];
    }
}

// ---------------- bf16 pack helper ------------------------------------------
__device__ __forceinline__ unsigned pack_bf16(float lo, float hi) {
    __nv_bfloat162 v = __floats2bfloat162_rn(lo, hi);
    return *(unsigned*)&v;
}

// ===== FP8 GEMM layer 1: BM=128, BN=256, 512 thr, m16n8k32 e4m3 =============
__global__ void __launch_bounds__(512) fp8_gemm_n256(const float* __restrict__ A,
                                                     const float* __restrict__ B,
                                                     __nv_fp8_storage_t* __restrict__ Cout,
                                                     int M, int K) {
    const int N = 256;
    __shared__ unsigned As_q[2][128][12];
    __shared__ unsigned Bs_q[2][8][264];

    const int tid  = threadIdx.x;
    const int warp = tid >> 5;
    const int lane = tid & 31;
    const int gid  = lane >> 2;
    const int tig  = lane & 3;
    const int wm   = warp & 1;
    const int wn   = warp >> 1;
    const int bm   = blockIdx.y * 128;

    const int am  = tid >> 2;
    const int ak8 = tid & 3;
    const int bkq = tid >> 6;
    const int bn4 = (tid & 63) * 4;

    float acc[4][4][4];
#pragma unroll
    for (int i = 0; i < 4; i++)
#pragma unroll
        for (int j = 0; j < 4; j++)
#pragma unroll
            for (int q = 0; q < 4; q++) acc[i][j][q] = 0.0f;

    const int nIter = K / 32;
    float4 la0, la1;
    float4 lb[4];

    auto load_regs = [&](int it) {
        int k0 = it * 32;
        if (bm + am < M) {
            const float* ap = A + (size_t)(bm + am) * K + k0 + ak8 * 8;
            la0 = *(const float4*)ap;
            la1 = *(const float4*)(ap + 4);
        } else {
            la0 = make_float4(0.f, 0.f, 0.f, 0.f); la1 = la0;
        }
        const float* bp = B + (size_t)(k0 + bkq * 4) * N + bn4;
#pragma unroll
        for (int r = 0; r < 4; r++)
            lb[r] = *(const float4*)(bp + (size_t)r * N);
    };

    auto store_smem = [&](int buf) {
        As_q[buf][am][ak8 * 2 + 0] = pack_fp8x4(la0.x, la0.y, la0.z, la0.w);
        As_q[buf][am][ak8 * 2 + 1] = pack_fp8x4(la1.x, la1.y, la1.z, la1.w);
        uint4 o;
        o.x = pack_fp8x4(lb[0].x * W1_SCALE, lb[1].x * W1_SCALE,
                         lb[2].x * W1_SCALE, lb[3].x * W1_SCALE);
        o.y = pack_fp8x4(lb[0].y * W1_SCALE, lb[1].y * W1_SCALE,
                         lb[2].y * W1_SCALE, lb[3].y * W1_SCALE);
        o.z = pack_fp8x4(lb[0].z * W1_SCALE, lb[1].z * W1_SCALE,
                         lb[2].z * W1_SCALE, lb[3].z * W1_SCALE);
        o.w = pack_fp8x4(lb[0].w * W1_SCALE, lb[1].w * W1_SCALE,
                         lb[2].w * W1_SCALE, lb[3].w * W1_SCALE);
        *(uint4*)&Bs_q[buf][bkq][bn4] = o;
    };

    load_regs(0);
    store_smem(0);
    __syncthreads();

    for (int it = 0; it < nIter; it++) {
        int buf = it & 1;
        bool hasNext = (it + 1) < nIter;
        if (hasNext) load_regs(it + 1);

        unsigned af[4][4], bf[4][2];
#pragma unroll
        for (int im = 0; im < 4; im++) {
            int m = wm * 64 + im * 16 + gid;
            af[im][0] = As_q[buf][m][tig];
            af[im][1] = As_q[buf][m + 8][tig];
            af[im][2] = As_q[buf][m][tig + 4];
            af[im][3] = As_q[buf][m + 8][tig + 4];
        }
#pragma unroll
        for (int in_ = 0; in_ < 4; in_++) {
            int n = wn * 32 + in_ * 8 + gid;
            bf[in_][0] = Bs_q[buf][tig][n];
            bf[in_][1] = Bs_q[buf][tig + 4][n];
        }
#pragma unroll
        for (int im = 0; im < 4; im++)
#pragma unroll
            for (int in_ = 0; in_ < 4; in_++) {
                asm volatile(
                    "mma.sync.aligned.m16n8k32.row.col.f32.e4m3.e4m3.f32 "
                    "{%0,%1,%2,%3}, {%4,%5,%6,%7}, {%8,%9}, {%0,%1,%2,%3};"
                    : "+f"(acc[im][in_][0]), "+f"(acc[im][in_][1]),
                      "+f"(acc[im][in_][2]), "+f"(acc[im][in_][3])
                    : "r"(af[im][0]), "r"(af[im][1]),
                      "r"(af[im][2]), "r"(af[im][3]),
                      "r"(bf[in_][0]), "r"(bf[in_][1]));
            }

        if (hasNext) {
            store_smem((it + 1) & 1);
            __syncthreads();
        }
    }

#pragma unroll
    for (int im = 0; im < 4; im++) {
        int r0 = bm + wm * 64 + im * 16 + gid;
        int r1 = r0 + 8;
#pragma unroll
        for (int in_ = 0; in_ < 4; in_++) {
            int c = wn * 32 + in_ * 8 + 2 * tig;
            if (r0 < M)
                *(unsigned short*)(Cout + (size_t)r0 * N + c) =
                    float2_to_fp8x2(acc[im][in_][0] * W1_SCALE_INV,
                                    acc[im][in_][1] * W1_SCALE_INV);
            if (r1 < M)
                *(unsigned short*)(Cout + (size_t)r1 * N + c) =
                    float2_to_fp8x2(acc[im][in_][2] * W1_SCALE_INV,
                                    acc[im][in_][3] * W1_SCALE_INV);
        }
    }
}

// ===== BF16 GEMM layer 2: BM=128, BN=128, A bf16 k-pair packed ==============
__global__ void __launch_bounds__(256) bf16_gemm_abf16(const __nv_bfloat16* __restrict__ A,
                                                       const float* __restrict__ B,
                                                       __nv_fp8_storage_t* __restrict__ Cout,
                                                       int M, int K, int N) {
    __shared__ unsigned As_p[2][128][12];
    __shared__ unsigned Bs_p[2][8][136];

    const int tid  = threadIdx.x;
    const int warp = tid >> 5;
    const int lane = tid & 31;
    const int gid  = lane >> 2;
    const int tig  = lane & 3;
    const int wm   = warp & 1;
    const int wn   = warp >> 1;
    const int bm   = blockIdx.y * 128;
    const int bn   = blockIdx.x * 128;

    const int am = tid >> 1;
    const int akh = tid & 1;
    const int bw = warp;
    const int bn4 = lane * 4;

    float acc[4][4][4];
#pragma unroll
    for (int i = 0; i < 4; i++)
#pragma unroll
        for (int j = 0; j < 4; j++)
#pragma unroll
            for (int q = 0; q < 4; q++) acc[i][j][q] = 0.0f;

    const int nIter = K / 16;
    uint4 laq;
    float4 lb0, lb1;

    auto load_regs = [&](int it) {
        if (bm + am < M)
            laq = ((const uint4*)(A + (size_t)(bm + am) * K))[it * 2 + akh];
        else
            laq = make_uint4(0u, 0u, 0u, 0u);
        int k0 = it * 16;
        const float* bp = B + (size_t)(k0 + 2 * bw) * N + bn + bn4;
        lb0 = *(const float4*)bp;
        lb1 = *(const float4*)(bp + N);
    };

    auto store_smem = [&](int buf) {
        *(uint4*)&As_p[buf][am][akh * 4] = laq;
        unsigned ub0 = pack_bf16(lb0.x, lb1.x);
        unsigned ub1 = pack_bf16(lb0.y, lb1.y);
        unsigned ub2 = pack_bf16(lb0.z, lb1.z);
        unsigned ub3 = pack_bf16(lb0.w, lb1.w);
        *(uint4*)&Bs_p[buf][bw][bn4] = make_uint4(ub0, ub1, ub2, ub3);
    };

    load_regs(0);
    store_smem(0);
    __syncthreads();

    for (int it = 0; it < nIter; it++) {
        int buf = it & 1;
        bool hasNext = (it + 1) < nIter;
        if (hasNext) load_regs(it + 1);

        unsigned af[4][4], bf[4][2];
#pragma unroll
        for (int im = 0; im < 4; im++) {
            int m = wm * 64 + im * 16 + gid;
            af[im][0] = As_p[buf][m][tig];
            af[im][1] = As_p[buf][m + 8][tig];
            af[im][2] = As_p[buf][m][tig + 4];
            af[im][3] = As_p[buf][m + 8][tig + 4];
        }
#pragma unroll
        for (int in_ = 0; in_ < 4; in_++) {
            int n = wn * 32 + in_ * 8 + gid;
            bf[in_][0] = Bs_p[buf][tig][n];
            bf[in_][1] = Bs_p[buf][tig + 4][n];
        }
#pragma unroll
        for (int im = 0; im < 4; im++)
#pragma unroll
            for (int in_ = 0; in_ < 4; in_++) {
                asm volatile(
                    "mma.sync.aligned.m16n8k16.row.col.f32.bf16.bf16.f32 "
                    "{%0,%1,%2,%3}, {%4,%5,%6,%7}, {%8,%9}, {%0,%1,%2,%3};"
                    : "+f"(acc[im][in_][0]), "+f"(acc[im][in_][1]),
                      "+f"(acc[im][in_][2]), "+f"(acc[im][in_][3])
                    : "r"(af[im][0]), "r"(af[im][1]),
                      "r"(af[im][2]), "r"(af[im][3]),
                      "r"(bf[in_][0]), "r"(bf[in_][1]));
            }

        if (hasNext) {
            store_smem((it + 1) & 1);
            __syncthreads();
        }
    }

#pragma unroll
    for (int im = 0; im < 4; im++) {
        int r0 = bm + wm * 64 + im * 16 + gid;
        int r1 = r0 + 8;
#pragma unroll
        for (int in_ = 0; in_ < 4; in_++) {
            int c = bn + wn * 32 + in_ * 8 + 2 * tig;
            if (r0 < M)
                *(unsigned short*)(Cout + (size_t)r0 * N + c) =
                    float2_to_fp8x2(acc[im][in_][0], acc[im][in_][1]);
            if (r1 < M)
                *(unsigned short*)(Cout + (size_t)r1 * N + c) =
                    float2_to_fp8x2(acc[im][in_][2], acc[im][in_][3]);
        }
    }
}

// ---------------- CSR gather aggregation (fp8 in, half2 accumulate) ---------
// warp per node, 2-edge unroll; lane owns 8 channels (4 half2 accumulators).
__global__ void __launch_bounds__(256) k_gather256(const __nv_fp8_storage_t* __restrict__ h,
                                                   const float* __restrict__ bias,
                                                   __nv_bfloat16* __restrict__ out) {
    const int node = (blockIdx.x * blockDim.x + threadIdx.x) >> 5;
    const int lane = threadIdx.x & 31;
    if (node >= N_NODES) return;

    __half2 acc[4];
#pragma unroll
    for (int i = 0; i < 4; i++) acc[i] = __float2half2_rn(0.f);

#define ACC256(q, w2) { \
        acc[0] = __hfma2(fp8x2_to_half2((unsigned short)((q).x & 0xFFFF)), (w2), acc[0]); \
        acc[1] = __hfma2(fp8x2_to_half2((unsigned short)((q).x >> 16)),    (w2), acc[1]); \
        acc[2] = __hfma2(fp8x2_to_half2((unsigned short)((q).y & 0xFFFF)), (w2), acc[2]); \
        acc[3] = __hfma2(fp8x2_to_half2((unsigned short)((q).y >> 16)),    (w2), acc[3]); }

    const int e0 = g_off[node];
    const int e1 = g_off[node + 1];
    int e = e0;
    for (; e + 2 <= e1; e += 2) {
        int s0 = g_csr[e];
        int s1 = g_csr[e + 1];
        __half2 w0 = __float2half2_rn(g_dinv[s0]);
        __half2 w1 = __float2half2_rn(g_dinv[s1]);
        uint2 q0 = ((const uint2*)(h + (size_t)s0 * C1))[lane];
        uint2 q1 = ((const uint2*)(h + (size_t)s1 * C1))[lane];
        ACC256(q0, w0)
        ACC256(q1, w1)
    }
    if (e < e1) {
        int s = g_csr[e];
        __half2 w = __float2half2_rn(g_dinv[s]);
        uint2 q = ((const uint2*)(h + (size_t)s * C1))[lane];
        ACC256(q, w)
    }
#undef ACC256

    float2 a01 = __half22float2(acc[0]);
    float2 a23 = __half22float2(acc[1]);
    float2 a45 = __half22float2(acc[2]);
    float2 a67 = __half22float2(acc[3]);
    float af[8] = {a01.x, a01.y, a23.x, a23.y, a45.x, a45.y, a67.x, a67.y};

    float dd = g_dinv[node];
    uint2 qs = ((const uint2*)(h + (size_t)node * C1))[lane];
    float2 f0 = fp8x2_to_float2((unsigned short)(qs.x & 0xFFFF));
    float2 f1 = fp8x2_to_float2((unsigned short)(qs.x >> 16));
    float2 f2 = fp8x2_to_float2((unsigned short)(qs.y & 0xFFFF));
    float2 f3 = fp8x2_to_float2((unsigned short)(qs.y >> 16));
    float sf[8] = {f0.x, f0.y, f1.x, f1.y, f2.x, f2.y, f3.x, f3.y};

    float4 b0 = ((const float4*)bias)[lane * 2 + 0];
    float4 b1 = ((const float4*)bias)[lane * 2 + 1];
    float bb[8] = {b0.x, b0.y, b0.z, b0.w, b1.x, b1.y, b1.z, b1.w};

    float r[8];
#pragma unroll
    for (int i = 0; i < 8; i++)
        r[i] = fmaxf((af[i] + sf[i] * dd) * dd + bb[i], 0.f);

    uint4 o;
    o.x = pack_bf16(r[0], r[1]);
    o.y = pack_bf16(r[2], r[3]);
    o.z = pack_bf16(r[4], r[5]);
    o.w = pack_bf16(r[6], r[7]);
    ((uint4*)(out + (size_t)node * C1))[lane] = o;
}

// warp per node, 4-edge unroll; lane owns 4 channels (2 half2 accumulators).
// FUSED layer-3 GEMM via warp reduction.
__global__ void __launch_bounds__(256) k_gather128_gemm3(
        const __nv_fp8_storage_t* __restrict__ h,
        const float* __restrict__ bias,
        const float* __restrict__ W3,
        float* __restrict__ h3out) {
    const int node = (blockIdx.x * blockDim.x + threadIdx.x) >> 5;
    const int lane = threadIdx.x & 31;
    if (node >= N_NODES) return;

    __half2 acc0 = __float2half2_rn(0.f);
    __half2 acc1 = __float2half2_rn(0.f);

#define ACC128(q, w2) { \
        acc0 = __hfma2(fp8x2_to_half2((unsigned short)((q) & 0xFFFF)), (w2), acc0); \
        acc1 = __hfma2(fp8x2_to_half2((unsigned short)((q) >> 16)),    (w2), acc1); }

    const int e0 = g_off[node];
    const int e1 = g_off[node + 1];
    int e = e0;
    for (; e + 4 <= e1; e += 4) {
        int s0 = g_csr[e], s1 = g_csr[e + 1], s2 = g_csr[e + 2], s3 = g_csr[e + 3];
        __half2 w0 = __float2half2_rn(g_dinv[s0]);
        __half2 w1 = __float2half2_rn(g_dinv[s1]);
        __half2 w2 = __float2half2_rn(g_dinv[s2]);
        __half2 w3 = __float2half2_rn(g_dinv[s3]);
        unsigned q0 = ((const unsigned*)(h + (size_t)s0 * C2))[lane];
        unsigned q1 = ((const unsigned*)(h + (size_t)s1 * C2))[lane];
        unsigned q2 = ((const unsigned*)(h + (size_t)s2 * C2))[lane];
        unsigned q3 = ((const unsigned*)(h + (size_t)s3 * C2))[lane];
        ACC128(q0, w0) ACC128(q1, w1) ACC128(q2, w2) ACC128(q3, w3)
    }
    for (; e < e1; e++) {
        int s = g_csr[e];
        __half2 w = __float2half2_rn(g_dinv[s]);
        unsigned q = ((const unsigned*)(h + (size_t)s * C2))[lane];
        ACC128(q, w)
    }
#undef ACC128

    float2 a01 = __half22float2(acc0);
    float2 a23 = __half22float2(acc1);
    float af[4] = {a01.x, a01.y, a23.x, a23.y};

    float dd = g_dinv[node];
    unsigned qs = ((const unsigned*)(h + (size_t)node * C2))[lane];
    float2 f0 = fp8x2_to_float2((unsigned short)(qs & 0xFFFF));
    float2 f1 = fp8x2_to_float2((unsigned short)(qs >> 16));
    float sf[4] = {f0.x, f0.y, f1.x, f1.y};

    float4 b = ((const float4*)bias)[lane];
    float bb[4] = {b.x, b.y, b.z, b.w};

    float r[4];
#pragma unroll
    for (int i = 0; i < 4; i++)
        r[i] = fmaxf((af[i] + sf[i] * dd) * dd + bb[i], 0.f);

    float h30 = 0.f, h31 = 0.f;
#pragma unroll
    for (int i = 0; i < 4; i++) {
        float2 wv = ((const float2*)W3)[lane * 4 + i];
        h30 += r[i] * wv.x;
        h31 += r[i] * wv.y;
    }
#pragma unroll
    for (int o = 16; o > 0; o >>= 1) {
        h30 += __shfl_down_sync(0xffffffffu, h30, o);
        h31 += __shfl_down_sync(0xffffffffu, h31, o);
    }
    if (lane == 0)
        ((float2*)h3out)[node] = make_float2(h30, h31);
}

__global__ void __launch_bounds__(256) k_gather2_sig(const float* __restrict__ h,
                                                     const float* __restrict__ bias,
                                                     float* __restrict__ out) {
    const int node = (blockIdx.x * blockDim.x + threadIdx.x) >> 5;
    const int lane = threadIdx.x & 31;
    if (node >= N_NODES) return;

    float a0 = 0.f, a1 = 0.f;
    const int e0 = g_off[node];
    const int e1 = g_off[node + 1];
    for (int e = e0 + lane; e < e1; e += 32) {
        int s = g_csr[e];
        float w = g_dinv[s];
        float2 f = ((const float2*)h)[s];
        a0 += f.x * w;
        a1 += f.y * w;
    }
#pragma unroll
    for (int o = 16; o > 0; o >>= 1) {
        a0 += __shfl_down_sync(0xffffffffu, a0, o);
        a1 += __shfl_down_sync(0xffffffffu, a1, o);
    }
    if (lane == 0) {
        float dd = g_dinv[node];
        float2 f = ((const float2*)h)[node];
        float r0 = (a0 + f.x * dd) * dd + bias[0];
        float r1 = (a1 + f.y * dd) * dd + bias[1];
        float2 o2;
        o2.x = 1.0f / (1.0f + expf(-r0));
        o2.y = 1.0f / (1.0f + expf(-r1));
        ((float2*)out)[node] = o2;
    }
}

// ---------------- launch ----------------------------------------------------
extern "C" void kernel_launch(void* const* d_in, const int* in_sizes, int n_in,
                              void* d_out, int out_size) {
    const float* x  = (const float*)d_in[0];
    const int*   ei = (const int*)d_in[1];
    const float* W1 = (const float*)d_in[2];
    const float* b1 = (const float*)d_in[3];
    const float* W2 = (const float*)d_in[4];
    const float* b2 = (const float*)d_in[5];
    const float* W3 = (const float*)d_in[6];
    const float* b3 = (const float*)d_in[7];
    float* out = (float*)d_out;

    const int* src = ei;
    const int* dst = ei + N_EDGES;

    __nv_fp8_storage_t* h1; cudaGetSymbolAddress((void**)&h1, g_h1);
    __nv_bfloat16* a1;      cudaGetSymbolAddress((void**)&a1, g_a1);
    __nv_fp8_storage_t* h2; cudaGetSymbolAddress((void**)&h2, g_h2);
    float* h3;              cudaGetSymbolAddress((void**)&h3, g_h3);

    // one-time host resources (created on the uncaptured correctness call)
    static cudaStream_t s2 = nullptr;
    static cudaEvent_t ev_fork = nullptr, ev_join = nullptr;
    static bool init_done = false;
    if (!init_done) {
        cudaStreamCreateWithFlags(&s2, cudaStreamNonBlocking);
        cudaEventCreateWithFlags(&ev_fork, cudaEventDisableTiming);
        cudaEventCreateWithFlags(&ev_join, cudaEventDisableTiming);
        init_done = true;
    }

    const int T = 256;

    // ---- fork: CSR build on s2, GEMM1 on main stream (independent work)
    cudaEventRecord(ev_fork, 0);
    cudaStreamWaitEvent(s2, ev_fork, 0);

    k_zero_cnt<<<(N_NODES + T - 1) / T, T, 0, s2>>>();
    k_count<<<(N_EDGES + T - 1) / T, T, 0, s2>>>(dst);
    k_scan<<<1, SCAN_T, 0, s2>>>();
    k_fill<<<(N_EDGES + T - 1) / T, T, 0, s2>>>(src, dst);
    cudaEventRecord(ev_join, s2);

    // ---- layer 1 GEMM: fp8 tensor cores, fp8 out
    {
        dim3 grid(1, (N_NODES + 127) / 128);
        fp8_gemm_n256<<<grid, 512>>>(x, W1, h1, N_NODES, C_IN);
    }

    // ---- join: gather needs both CSR and h1
    cudaStreamWaitEvent(0, ev_join, 0);

    k_gather256<<<(N_NODES * 32 + T - 1) / T, T>>>(h1, b1, a1);

    // ---- layer 2 GEMM (A bf16 packed), fp8 out
    {
        dim3 grid(1, (N_NODES + 127) / 128);
        bf16_gemm_abf16<<<grid, 256>>>(a1, W2, h2, N_NODES, C1, C2);
    }

    // ---- layer 2 aggregation + fused layer-3 GEMM
    k_gather128_gemm3<<<(N_NODES * 32 + T - 1) / T, T>>>(h2, b2, W3, h3);

    // ---- layer 3 aggregation + sigmoid
    k_gather2_sig<<<(N_NODES * 32 + T - 1) / T, T>>>(h3, b3, out);
}